// round 14
// baseline (speedup 1.0000x reference)
#include <cuda_runtime.h>
#include <cuda_fp16.h>
#include <cstdint>
#include <math.h>

// ---------------- problem constants ----------------
#define NSAMP 256
#define CIN   2304
#define CH    512
#define HW    49
#define NG    16
#define GSZ   16
#define K_RED (CIN*9)    // 20736
#define K_CC  (CH*9)     // 4608
#define FEAT_ELEMS (NSAMP*CH*HW)   // 6422528
#define EPSG  1e-5f
#define ATT_SCALE 0.044194173824159216f  // 1/sqrt(512)

// ---------------- scratch (device globals; no allocation) ----------------
// feat is CHANNEL-LAST fp32 (only consumer: out-conv addsrc).
// k/v and virt are CHANNEL-LAST [n][p][c].
__device__ float g_feat [FEAT_ELEMS];
__device__ float g_k1   [FEAT_ELEMS];   // also reduce-conv partial 0 (NCHW)
__device__ float g_v1   [FEAT_ELEMS];   // also reduce-conv partial 1 (NCHW)
__device__ float g_k2   [FEAT_ELEMS];   // also reduce-conv partial 2 (NCHW)
__device__ float g_v2   [FEAT_ELEMS];
__device__ float g_vir1 [FEAT_ELEMS];
__device__ float g_vir2 [FEAT_ELEMS];
__device__ float g_stats[1024];
__device__ float g_wq[2*9*512*5];       // q-conv collapsed weights

// padded channel-last activations: [n][81][C], fp16; borders stay zero
__device__ __align__(256) __half g_bpad [NSAMP*81*CIN];
__device__ __align__(256) __half g_fpad [NSAMP*81*CH];
__device__ __align__(256) __half g_h1pad[NSAMP*81*CH];
__device__ __align__(256) __half g_h2pad[NSAMP*81*CH];

// fp16 weights, tap-major layout [co][tap][ci]
__device__ __align__(256) __half g_wR [K_RED*CH];
__device__ __align__(256) __half g_wK1[K_CC*CH];
__device__ __align__(256) __half g_wV1[K_CC*CH];
__device__ __align__(256) __half g_wK2[K_CC*CH];
__device__ __align__(256) __half g_wV2[K_CC*CH];
__device__ __align__(256) __half g_wC1[K_CC*CH];
__device__ __align__(256) __half g_wC2[K_CC*CH];

// ---------------- helpers ----------------
__device__ __forceinline__ uint32_t smem_u32(const void* p) {
    uint32_t a;
    asm("{ .reg .u64 t; cvta.to.shared.u64 t, %1; cvt.u32.u64 %0, t; }" : "=r"(a) : "l"(p));
    return a;
}
__device__ __forceinline__ void cp_async16(uint32_t dst, const void* src) {
    asm volatile("cp.async.cg.shared.global [%0], [%1], 16;" :: "r"(dst), "l"(src));
}
__device__ __forceinline__ void ldm_x4(uint32_t* r, uint32_t addr) {
    asm volatile("ldmatrix.sync.aligned.m8n8.x4.shared.b16 {%0,%1,%2,%3}, [%4];"
        : "=r"(r[0]), "=r"(r[1]), "=r"(r[2]), "=r"(r[3]) : "r"(addr));
}
__device__ __forceinline__ void mma_f16(float* d, const uint32_t* a, const uint32_t* b) {
    asm volatile(
        "mma.sync.aligned.m16n8k16.row.col.f32.f16.f16.f32 "
        "{%0,%1,%2,%3}, {%4,%5,%6,%7}, {%8,%9}, {%0,%1,%2,%3};\n"
        : "+f"(d[0]), "+f"(d[1]), "+f"(d[2]), "+f"(d[3])
        : "r"(a[0]), "r"(a[1]), "r"(a[2]), "r"(a[3]), "r"(b[0]), "r"(b[1]));
}

// -------- coalesced weight reorder + fp16 round: w[co][ci*9+t] -> wh[co][t*C+ci]
struct WReorder2 {
    const float* src[7];
    __half* dst[7];
    int C[7];
    int sidx[21];
    int ci0[21];
};
__global__ void conv_w_reorder2(WReorder2 R) {
    int s = R.sidx[blockIdx.x];
    int ci0 = R.ci0[blockIdx.x];
    int co = blockIdx.y;
    int C = R.C[s];
    int K9 = 9 * C;
    const float* src = R.src[s] + (size_t)co * K9 + (size_t)ci0 * 9;
    __half* dst = R.dst[s] + (size_t)co * K9;
    __shared__ float sm[2304];
    int tid = threadIdx.x;
#pragma unroll
    for (int i = 0; i < 9; i++) sm[tid + 256 * i] = src[tid + 256 * i];
    __syncthreads();
#pragma unroll
    for (int t = 0; t < 9; t++)
        dst[t * C + ci0 + tid] = __float2half_rn(sm[tid * 9 + t]);
}

// ---------------- q-conv weight collapse: Wq[br][cls][co][ci] ----------------
__global__ void qw_prep(const float* __restrict__ wq1, const float* __restrict__ wq2,
                        float* __restrict__ Wq) {
    int i = blockIdx.x * 256 + threadIdx.x;
    if (i >= 2 * 9 * 512) return;
    int br = i / (9 * 512);
    int rem = i - br * 9 * 512;
    int cls = rem / 512, co = rem - cls * 512;
    int cy = cls / 3, cx = cls - 3 * cy;
    const float* w = (br ? wq2 : wq1) + co * 45;
#pragma unroll
    for (int ci = 0; ci < 5; ci++) {
        float s = 0.f;
#pragma unroll
        for (int dy = 0; dy < 3; dy++) {
            if (cy == 0 && dy == 0) continue;
            if (cy == 2 && dy == 2) continue;
#pragma unroll
            for (int dx = 0; dx < 3; dx++) {
                if (cx == 0 && dx == 0) continue;
                if (cx == 2 && dx == 2) continue;
                s += w[ci * 9 + dy * 3 + dx];
            }
        }
        Wq[((br * 9 + cls) * 512 + co) * 5 + ci] = s;
    }
}

// ---------------- NCHW float -> padded channel-last fp16 (interior only) ------
__global__ void pad_convert(const float* __restrict__ src, __half* __restrict__ hi, int C) {
    int n = blockIdx.x, c0 = blockIdx.y * 64;
    __shared__ float tile[64][51];
    int tid = threadIdx.x;
    for (int e = tid; e < 64 * 49; e += 256) {
        int ci = e / 49, p = e - 49 * ci;
        tile[ci][p] = src[((size_t)n * C + c0 + ci) * 49 + p];
    }
    __syncthreads();
    for (int e = tid; e < 49 * 64; e += 256) {
        int p = e >> 6, ci = e & 63;
        int y = p / 7, x = p - 7 * y;
        hi[((size_t)n * 81 + (y + 1) * 9 + (x + 1)) * C + c0 + ci] =
            __float2half_rn(tile[ci][p]);
    }
}

// -------- combine 3 NCHW partials -> featCL (channel-last fp32) + fpad (fp16) --
__global__ void combine3_pad(const float* __restrict__ p0, const float* __restrict__ p1,
                             const float* __restrict__ p2,
                             float* __restrict__ featCL, __half* __restrict__ fpad) {
    int n = blockIdx.x, c0 = blockIdx.y * 64;
    __shared__ float tile[64][51];
    int tid = threadIdx.x;
    for (int e = tid; e < 64 * 49; e += 256) {
        int ci = e / 49, p = e - 49 * ci;
        size_t idx = ((size_t)n * CH + c0 + ci) * 49 + p;
        tile[ci][p] = p0[idx] + p1[idx] + p2[idx];
    }
    __syncthreads();
    for (int e = tid; e < 49 * 64; e += 256) {
        int p = e >> 6, ci = e & 63;
        float v = tile[ci][p];
        featCL[((size_t)n * 49 + p) * CH + c0 + ci] = v;        // channel-last, coalesced
        int y = p / 7, x = p - 7 * y;
        fpad[((size_t)n * 81 + (y + 1) * 9 + (x + 1)) * CH + c0 + ci] =
            __float2half_rn(v);
    }
}

// ------- fused GN-normalize + relu + pad-convert, channel-last, elementwise ---
__global__ void norm_relu_pad(const float* __restrict__ x1, const float* __restrict__ x2,
                              const float* __restrict__ stats,
                              const float* __restrict__ gamma, const float* __restrict__ beta,
                              __half* __restrict__ h1, __half* __restrict__ h2) {
    int idx = blockIdx.x * 256 + threadIdx.x;
    if (idx >= FEAT_ELEMS) return;
    int br = blockIdx.y;
    const float* x = br ? x2 : x1;
    __half* hp = br ? h2 : h1;
    int c = idx & 511;
    int t = idx >> 9;
    int n = t / 49, p = t - 49 * n;
    float mu = stats[br * 512 + n];
    float rs = stats[br * 512 + 256 + n];
    float v = fmaxf((x[idx] - mu) * rs * gamma[c] + beta[c], 0.f);
    int y = p / 7, xq = p - 7 * y;
    hp[((size_t)n * 81 + (y + 1) * 9 + (xq + 1)) * CH + c] = __float2half_rn(v);
}

// ---------------- batched HMMA conv: shifted 1x1 GEMMs over padded input ------
// outmode: 0 = NCHW direct store (reduce-conv partials, no addsrc)
//          1 = channel-last float2 store
//          2 = NCHW via SMEM transpose, addsrc read channel-last
#define KC   64
#define KCP  72
#define MATH (128*KCP)
#define BUFE (2*MATH)
#define NSTG 3
#define SMEM_BYTES (NSTG*BUFE*2)     // 110592 bytes

struct ConvBatch {
    const __half* a[4];
    const __half* wh[4];
    float* out[4];
    const float* addsrc;             // channel-last fp32 (mode 2) or null
    int tap0[4];
    int outmode;
};

__global__ void __launch_bounds__(256, 2)
conv_mma(ConvBatch P, int C, int ntap) {
    extern __shared__ __half smem[];
    const int K9 = 9 * C;
    const int NCI = C / KC;
    const int NQ = ntap * NCI;
    const int cv = blockIdx.z;
    const __half* __restrict__ A  = P.a[cv];
    const __half* __restrict__ Wh = P.wh[cv];
    float* __restrict__ out = P.out[cv];
    const float* addsrc = P.addsrc;
    const int tap0 = P.tap0[cv];

    const int tid = threadIdx.x;
    const int wid = tid >> 5, lane = tid & 31;
    const int g = lane >> 2, tg = lane & 3;
    const int m0 = blockIdx.x * 128;
    const int n0 = blockIdx.y * 128;
    const int wm = (wid & 1) * 64;
    const int wn = (wid >> 1) * 32;

    const int seg = tid & 7;
    const int r0 = tid >> 3;
    size_t abase[4];
#pragma unroll
    for (int h = 0; h < 4; h++) {
        int m = m0 + r0 + 32 * h;
        int n = m / 49, p = m - 49 * n;
        int y = p / 7, x = p - 7 * y;
        abase[h] = ((size_t)n * 81 + y * 9 + x) * C + seg * 8;
    }

    const int aRow = wm + (lane & 15);
    const int aCol = (lane >> 4) * 8;
    const int bRow = wn + (lane & 7) + ((lane >> 4) * 8);
    const int bCol = ((lane >> 3) & 1) * 8;

    auto fill = [&](int q) {
        __half* base = smem + (q % NSTG) * BUFE;
        int t = tap0 + q / NCI;
        int ci = (q % NCI) * KC;
        int a3 = t / 3, b3 = t - 3 * a3;
        size_t tof = (size_t)(a3 * 9 + b3) * C + ci;
#pragma unroll
        for (int h = 0; h < 4; h++) {
            int r = r0 + 32 * h;
            cp_async16(smem_u32(&base[r * KCP + seg * 8]), A + abase[h] + tof);
        }
#pragma unroll
        for (int h = 0; h < 4; h++) {
            int row = r0 + 32 * h;
            size_t src = (size_t)(n0 + row) * K9 + t * C + ci + seg * 8;
            cp_async16(smem_u32(&base[MATH + row * KCP + seg * 8]), Wh + src);
        }
        asm volatile("cp.async.commit_group;" ::: "memory");
    };

    float acc[4][4][4];
#pragma unroll
    for (int t = 0; t < 4; t++)
#pragma unroll
        for (int u = 0; u < 4; u++)
#pragma unroll
            for (int e = 0; e < 4; e++) acc[t][u][e] = 0.f;

    fill(0);
    if (NQ > 1) fill(1);

    for (int q = 0; q < NQ; q++) {
        if (q + 1 < NQ) asm volatile("cp.async.wait_group 1;" ::: "memory");
        else            asm volatile("cp.async.wait_group 0;" ::: "memory");
        __syncthreads();
        if (q + 2 < NQ) fill(q + 2);

        __half* cur = smem + (q % NSTG) * BUFE;
        uint32_t aB = smem_u32(cur);
        uint32_t bB = aB + MATH * 2;
#pragma unroll
        for (int s = 0; s < 4; s++) {
            uint32_t bregs[8];
            ldm_x4(bregs,     bB + (uint32_t)((bRow)      * KCP + 16 * s + bCol) * 2);
            ldm_x4(bregs + 4, bB + (uint32_t)((bRow + 16) * KCP + 16 * s + bCol) * 2);
#pragma unroll
            for (int t = 0; t < 4; t++) {
                uint32_t ar[4];
                ldm_x4(ar, aB + (uint32_t)((aRow + 16 * t) * KCP + 16 * s + aCol) * 2);
#pragma unroll
                for (int u = 0; u < 4; u++)
                    mma_f16(acc[t][u], ar, bregs + 2 * u);
            }
        }
    }

    // ---- epilogue ----
    if (P.outmode == 1) {
        // channel-last [n][p][c]: coalesced float2 stores
#pragma unroll
        for (int t = 0; t < 4; t++) {
#pragma unroll
            for (int h = 0; h < 2; h++) {
                int row = m0 + wm + 16 * t + g + 8 * h;
                size_t base = (size_t)row * CH;
#pragma unroll
                for (int u = 0; u < 4; u++) {
                    int col = n0 + wn + 8 * u + tg * 2;
                    float2 v2 = make_float2(acc[t][u][2 * h], acc[t][u][2 * h + 1]);
                    *reinterpret_cast<float2*>(&out[base + col]) = v2;
                }
            }
        }
    } else if (P.outmode == 0) {
        // NCHW direct (R12 behavior, reduce-conv partials)
#pragma unroll
        for (int t = 0; t < 4; t++) {
#pragma unroll
            for (int h = 0; h < 2; h++) {
                int row = m0 + wm + 16 * t + g + 8 * h;
                int n = row / 49, p = row - 49 * n;
                size_t base = (size_t)n * CH * 49 + p;
#pragma unroll
                for (int u = 0; u < 4; u++) {
                    int col = n0 + wn + 8 * u + tg * 2;
                    size_t i0 = base + (size_t)col * 49;
                    out[i0] = acc[t][u][2 * h];
                    out[i0 + 49] = acc[t][u][2 * h + 1];
                }
            }
        }
    } else {
        // NCHW via SMEM transpose; addsrc read channel-last (coalesced)
        float* sf = reinterpret_cast<float*>(smem);
        __syncthreads();                 // pipeline SMEM now free
#pragma unroll
        for (int t = 0; t < 4; t++) {
#pragma unroll
            for (int h = 0; h < 2; h++) {
                int row = wm + 16 * t + g + 8 * h;     // local row
#pragma unroll
                for (int u = 0; u < 4; u++) {
                    int col = wn + 8 * u + tg * 2;
                    float v0 = acc[t][u][2 * h];
                    float v1 = acc[t][u][2 * h + 1];
                    float2 a2 = *reinterpret_cast<const float2*>(
                        &addsrc[(size_t)(m0 + row) * CH + n0 + col]);
                    v0 += a2.x; v1 += a2.y;
                    sf[row * 129 + col] = v0;
                    sf[row * 129 + col + 1] = v1;
                }
            }
        }
        __syncthreads();
        for (int e = tid; e < 128 * 128; e += 256) {
            int co = e >> 7, m = e & 127;      // consecutive threads vary m -> coalesced
            int mm = m0 + m;
            int n = mm / 49, p = mm - 49 * n;
            out[(size_t)n * CH * 49 + (size_t)(n0 + co) * 49 + p] = sf[m * 129 + co];
        }
    }
}

// ------- attention per (hw, g, br); q computed on the fly from Wq x s5 --------
#define CCH 256
__global__ void attn2(const float* __restrict__ status, const float* __restrict__ rois,
                      const float* __restrict__ Wq,
                      const float* __restrict__ k1, const float* __restrict__ v1,
                      float* __restrict__ w1,
                      const float* __restrict__ k2, const float* __restrict__ v2,
                      float* __restrict__ w2) {
    int hw = blockIdx.x;
    int gg = blockIdx.y;
    int br = blockIdx.z;
    const float* k = br ? k2 : k1;
    const float* v = br ? v2 : v1;
    float* virt = br ? w2 : w1;

    int yy = hw / 7, xx = hw - 7 * yy;
    int cy = (yy == 0) ? 0 : ((yy == 6) ? 2 : 1);
    int cx = (xx == 0) ? 0 : ((xx == 6) ? 2 : 1);
    const float* WqBase = Wq + ((size_t)(br * 9 + cy * 3 + cx) * 512) * 5;

    __shared__ float bufA[GSZ][CCH + 1];
    __shared__ float bufB[GSZ][CCH + 1];
    __shared__ float att[GSZ][GSZ + 1];
    __shared__ float attn[GSZ][GSZ + 1];
    __shared__ float s5[GSZ][5];
    __shared__ float wqs[CCH][5];

    int tid = threadIdx.x;
    int i = tid >> 4, j = tid & 15;

    if (tid < GSZ * 5) {
        int r = tid / 5, ci = tid - 5 * r;
        int n = gg * GSZ + r;
        s5[r][ci] = (ci == 0) ? status[n * 2 + br] : rois[n * 5 + ci];
    }
    __syncthreads();

    float a = 0.f;
    for (int c0 = 0; c0 < CH; c0 += CCH) {
        for (int e = tid; e < CCH * 5; e += 256)
            wqs[e / 5][e % 5] = WqBase[(size_t)(c0 + e / 5) * 5 + (e % 5)];
        for (int e = tid; e < GSZ * CCH; e += 256) {
            int r = e >> 8, c = e & 255;
            bufB[r][c] = k[((size_t)(gg * GSZ + r) * 49 + hw) * CH + c0 + c];
        }
        __syncthreads();
        for (int e = tid; e < GSZ * CCH; e += 256) {
            int r = e >> 8, c = e & 255;
            bufA[r][c] = wqs[c][0] * s5[r][0] + wqs[c][1] * s5[r][1]
                       + wqs[c][2] * s5[r][2] + wqs[c][3] * s5[r][3]
                       + wqs[c][4] * s5[r][4];
        }
        __syncthreads();
#pragma unroll 8
        for (int c = 0; c < CCH; c++)
            a += bufA[i][c] * bufB[j][c];
        __syncthreads();
    }
    att[i][j] = a * ATT_SCALE;
    __syncthreads();

    float mx = att[i][0];
#pragma unroll
    for (int jj = 1; jj < GSZ; jj++) mx = fmaxf(mx, att[i][jj]);
    float sum = 0.f;
#pragma unroll
    for (int jj = 0; jj < GSZ; jj++) sum += expf(att[i][jj] - mx);
    attn[i][j] = expf(att[i][j] - mx) / sum;
    __syncthreads();

    for (int c0 = 0; c0 < CH; c0 += CCH) {
        for (int e = tid; e < GSZ * CCH; e += 256) {
            int r = e >> 8, c = e & 255;
            bufA[r][c] = v[((size_t)(gg * GSZ + r) * 49 + hw) * CH + c0 + c];
        }
        __syncthreads();
        for (int e = tid; e < GSZ * CCH; e += 256) {
            int r = e >> 8, c = e & 255;
            float s = 0.f;
#pragma unroll
            for (int jj = 0; jj < GSZ; jj++) s += attn[r][jj] * bufA[jj][c];
            virt[((size_t)(gg * GSZ + r) * 49 + hw) * CH + c0 + c] = s;
        }
        __syncthreads();
    }
}

// ---------------- groupnorm stats, both branches ----------
__global__ void gn_stats2(const float* __restrict__ x1, const float* __restrict__ x2,
                          float* __restrict__ stats) {
    __shared__ float ss[256], sq[256];
    int blk = blockIdx.x;
    int br = blk >> 8, n = blk & 255;
    const float* p = (br ? x2 : x1) + (size_t)n * CH * HW;
    float a = 0.f, b = 0.f;
    for (int e = threadIdx.x; e < CH * HW; e += 256) {
        float v = p[e];
        a += v; b += v * v;
    }
    ss[threadIdx.x] = a; sq[threadIdx.x] = b;
    __syncthreads();
    for (int s = 128; s > 0; s >>= 1) {
        if (threadIdx.x < s) { ss[threadIdx.x] += ss[threadIdx.x + s]; sq[threadIdx.x] += sq[threadIdx.x + s]; }
        __syncthreads();
    }
    if (threadIdx.x == 0) {
        float m = ss[0] / (float)(CH * HW);
        float var = sq[0] / (float)(CH * HW) - m * m;
        stats[br * 512 + n] = m;
        stats[br * 512 + 256 + n] = rsqrtf(var + EPSG);
    }
}

// ---------------- launcher ----------------
extern "C" void kernel_launch(void* const* d_in, const int* in_sizes, int n_in,
                              void* d_out, int out_size) {
    const float* status = (const float*)d_in[0];
    const float* rois   = (const float*)d_in[1];
    const float* bbox   = (const float*)d_in[2];
    const float* wR     = (const float*)d_in[3];
    const float* wQ1    = (const float*)d_in[4];
    const float* wQ2    = (const float*)d_in[5];
    const float* wK1    = (const float*)d_in[6];
    const float* wV1    = (const float*)d_in[7];
    const float* wK2    = (const float*)d_in[8];
    const float* wV2    = (const float*)d_in[9];
    const float* wC1    = (const float*)d_in[10];
    const float* wC2    = (const float*)d_in[11];
    const float* gamma  = (const float*)d_in[12];
    const float* beta   = (const float*)d_in[13];
    float* out1 = (float*)d_out;
    float* out2 = out1 + FEAT_ELEMS;

    float *feat, *k1, *v1, *k2, *v2, *vir1, *vir2, *stats, *wqv;
    cudaGetSymbolAddress((void**)&feat, g_feat);
    cudaGetSymbolAddress((void**)&k1,   g_k1);
    cudaGetSymbolAddress((void**)&v1,   g_v1);
    cudaGetSymbolAddress((void**)&k2,   g_k2);
    cudaGetSymbolAddress((void**)&v2,   g_v2);
    cudaGetSymbolAddress((void**)&vir1, g_vir1);
    cudaGetSymbolAddress((void**)&vir2, g_vir2);
    cudaGetSymbolAddress((void**)&stats, g_stats);
    cudaGetSymbolAddress((void**)&wqv,  g_wq);

    __half *bpad, *fpad, *h1p, *h2p;
    cudaGetSymbolAddress((void**)&bpad, g_bpad);
    cudaGetSymbolAddress((void**)&fpad, g_fpad);
    cudaGetSymbolAddress((void**)&h1p,  g_h1pad);
    cudaGetSymbolAddress((void**)&h2p,  g_h2pad);

    __half *whR, *whK1, *whV1, *whK2, *whV2, *whC1, *whC2;
    cudaGetSymbolAddress((void**)&whR,  g_wR);
    cudaGetSymbolAddress((void**)&whK1, g_wK1);
    cudaGetSymbolAddress((void**)&whV1, g_wV1);
    cudaGetSymbolAddress((void**)&whK2, g_wK2);
    cudaGetSymbolAddress((void**)&whV2, g_wV2);
    cudaGetSymbolAddress((void**)&whC1, g_wC1);
    cudaGetSymbolAddress((void**)&whC2, g_wC2);

    cudaFuncSetAttribute(conv_mma, cudaFuncAttributeMaxDynamicSharedMemorySize, SMEM_BYTES);

    // coalesced weight reorder + fp16 round (1 launch, all 7 weights)
    {
        WReorder2 R;
        R.src[0] = wR;  R.dst[0] = whR;  R.C[0] = CIN;
        R.src[1] = wK1; R.dst[1] = whK1; R.C[1] = CH;
        R.src[2] = wV1; R.dst[2] = whV1; R.C[2] = CH;
        R.src[3] = wK2; R.dst[3] = whK2; R.C[3] = CH;
        R.src[4] = wV2; R.dst[4] = whV2; R.C[4] = CH;
        R.src[5] = wC1; R.dst[5] = whC1; R.C[5] = CH;
        R.src[6] = wC2; R.dst[6] = whC2; R.C[6] = CH;
        int x = 0;
        for (int ci0 = 0; ci0 < CIN; ci0 += 256) { R.sidx[x] = 0; R.ci0[x] = ci0; x++; }
        for (int s = 1; s < 7; s++)
            for (int ci0 = 0; ci0 < CH; ci0 += 256) { R.sidx[x] = s; R.ci0[x] = ci0; x++; }
        conv_w_reorder2<<<dim3(x, CH), 256>>>(R);   // x = 21
    }

    // q-conv weight collapse
    qw_prep<<<(2 * 9 * 512 + 255) / 256, 256>>>(wQ1, wQ2, wqv);

    // pad-convert bbox
    pad_convert<<<dim3(NSAMP, CIN / 64), 256>>>(bbox, bpad, CIN);

    // reduce conv split-K=3 (NCHW partials, R12 epilogue)
    {
        ConvBatch P = {};
        for (int z = 0; z < 3; z++) { P.a[z] = bpad; P.wh[z] = whR; P.tap0[z] = 3 * z; }
        P.out[0] = k1; P.out[1] = v1; P.out[2] = k2;
        P.addsrc = nullptr; P.outmode = 0;
        conv_mma<<<dim3(NSAMP * HW / 128, CH / 128, 3), 256, SMEM_BYTES>>>(P, CIN, 3);
    }

    // combine partials -> featCL (channel-last fp32) + fpad (fp16 padded)
    combine3_pad<<<dim3(NSAMP, CH / 64), 256>>>(k1, v1, k2, feat, fpad);

    // k/v convs (4 fused), channel-last outputs
    {
        ConvBatch P = {};
        for (int i = 0; i < 4; i++) { P.a[i] = fpad; P.tap0[i] = 0; }
        P.wh[0] = whK1; P.out[0] = k1;
        P.wh[1] = whV1; P.out[1] = v1;
        P.wh[2] = whK2; P.out[2] = k2;
        P.wh[3] = whV2; P.out[3] = v2;
        P.addsrc = nullptr; P.outmode = 1;
        conv_mma<<<dim3(NSAMP * HW / 128, CH / 128, 4), 256, SMEM_BYTES>>>(P, CH, 9);
    }

    // attention (q fused from Wq x s5), both branches
    attn2<<<dim3(HW, NG, 2), 256>>>(status, rois, wqv, k1, v1, vir1, k2, v2, vir2);

    // groupnorm stats, both branches
    gn_stats2<<<512, 256>>>(vir1, vir2, stats);

    // fused normalize+relu+pad-convert, elementwise channel-last
    norm_relu_pad<<<dim3((FEAT_ELEMS + 255) / 256, 2), 256>>>(vir1, vir2, stats,
                                                              gamma, beta, h1p, h2p);

    // out convs (2 fused): out = featCL + conv(h, w_c), NCHW via SMEM transpose
    {
        ConvBatch P = {};
        P.a[0] = h1p; P.wh[0] = whC1; P.out[0] = out1; P.tap0[0] = 0;
        P.a[1] = h2p; P.wh[1] = whC2; P.out[1] = out2; P.tap0[1] = 0;
        P.addsrc = feat; P.outmode = 2;
        conv_mma<<<dim3(NSAMP * HW / 128, CH / 128, 2), 256, SMEM_BYTES>>>(P, CH, 9);
    }
}

// round 15
// speedup vs baseline: 1.0301x; 1.0301x over previous
#include <cuda_runtime.h>
#include <cuda_fp16.h>
#include <cstdint>
#include <math.h>

// ---------------- problem constants ----------------
#define NSAMP 256
#define CIN   2304
#define CH    512
#define HW    49
#define NG    16
#define GSZ   16
#define K_RED (CIN*9)    // 20736
#define K_CC  (CH*9)     // 4608
#define FEAT_ELEMS (NSAMP*CH*HW)   // 6422528
#define EPSG  1e-5f
#define ATT_SCALE 0.044194173824159216f  // 1/sqrt(512)

// ---------------- scratch (device globals; no allocation) ----------------
// feat is CHANNEL-LAST fp32 (only consumer: out-conv addsrc).
// k/v and virt are CHANNEL-LAST [n][p][c].
__device__ float g_feat [FEAT_ELEMS];
__device__ float g_k1   [FEAT_ELEMS];   // also reduce-conv partial 0 (NCHW)
__device__ float g_v1   [FEAT_ELEMS];   // also reduce-conv partial 1 (NCHW)
__device__ float g_k2   [FEAT_ELEMS];   // also reduce-conv partial 2 (NCHW)
__device__ float g_v2   [FEAT_ELEMS];
__device__ float g_vir1 [FEAT_ELEMS];
__device__ float g_vir2 [FEAT_ELEMS];
__device__ float g_stats[1024];
__device__ float g_wq[2*9*512*5];       // q-conv collapsed weights

// padded channel-last activations: [n][81][C], fp16; borders stay zero
__device__ __align__(256) __half g_bpad [NSAMP*81*CIN];
__device__ __align__(256) __half g_fpad [NSAMP*81*CH];
__device__ __align__(256) __half g_h1pad[NSAMP*81*CH];
__device__ __align__(256) __half g_h2pad[NSAMP*81*CH];

// fp16 weights, tap-major layout [co][tap][ci]
__device__ __align__(256) __half g_wR [K_RED*CH];
__device__ __align__(256) __half g_wK1[K_CC*CH];
__device__ __align__(256) __half g_wV1[K_CC*CH];
__device__ __align__(256) __half g_wK2[K_CC*CH];
__device__ __align__(256) __half g_wV2[K_CC*CH];
__device__ __align__(256) __half g_wC1[K_CC*CH];
__device__ __align__(256) __half g_wC2[K_CC*CH];

// ---------------- helpers ----------------
__device__ __forceinline__ uint32_t smem_u32(const void* p) {
    uint32_t a;
    asm("{ .reg .u64 t; cvta.to.shared.u64 t, %1; cvt.u32.u64 %0, t; }" : "=r"(a) : "l"(p));
    return a;
}
__device__ __forceinline__ void cp_async16(uint32_t dst, const void* src) {
    asm volatile("cp.async.cg.shared.global [%0], [%1], 16;" :: "r"(dst), "l"(src));
}
__device__ __forceinline__ void ldm_x4(uint32_t* r, uint32_t addr) {
    asm volatile("ldmatrix.sync.aligned.m8n8.x4.shared.b16 {%0,%1,%2,%3}, [%4];"
        : "=r"(r[0]), "=r"(r[1]), "=r"(r[2]), "=r"(r[3]) : "r"(addr));
}
__device__ __forceinline__ void mma_f16(float* d, const uint32_t* a, const uint32_t* b) {
    asm volatile(
        "mma.sync.aligned.m16n8k16.row.col.f32.f16.f16.f32 "
        "{%0,%1,%2,%3}, {%4,%5,%6,%7}, {%8,%9}, {%0,%1,%2,%3};\n"
        : "+f"(d[0]), "+f"(d[1]), "+f"(d[2]), "+f"(d[3])
        : "r"(a[0]), "r"(a[1]), "r"(a[2]), "r"(a[3]), "r"(b[0]), "r"(b[1]));
}

// -------- coalesced weight reorder + fp16 round: w[co][ci*9+t] -> wh[co][t*C+ci]
struct WReorder2 {
    const float* src[7];
    __half* dst[7];
    int C[7];
    int sidx[21];
    int ci0[21];
};
__global__ void conv_w_reorder2(WReorder2 R) {
    int s = R.sidx[blockIdx.x];
    int ci0 = R.ci0[blockIdx.x];
    int co = blockIdx.y;
    int C = R.C[s];
    int K9 = 9 * C;
    const float* src = R.src[s] + (size_t)co * K9 + (size_t)ci0 * 9;
    __half* dst = R.dst[s] + (size_t)co * K9;
    __shared__ float sm[2304];
    int tid = threadIdx.x;
#pragma unroll
    for (int i = 0; i < 9; i++) sm[tid + 256 * i] = src[tid + 256 * i];
    __syncthreads();
#pragma unroll
    for (int t = 0; t < 9; t++)
        dst[t * C + ci0 + tid] = __float2half_rn(sm[tid * 9 + t]);
}

// ---------------- q-conv weight collapse: Wq[br][cls][co][ci] ----------------
__global__ void qw_prep(const float* __restrict__ wq1, const float* __restrict__ wq2,
                        float* __restrict__ Wq) {
    int i = blockIdx.x * 256 + threadIdx.x;
    if (i >= 2 * 9 * 512) return;
    int br = i / (9 * 512);
    int rem = i - br * 9 * 512;
    int cls = rem / 512, co = rem - cls * 512;
    int cy = cls / 3, cx = cls - 3 * cy;
    const float* w = (br ? wq2 : wq1) + co * 45;
#pragma unroll
    for (int ci = 0; ci < 5; ci++) {
        float s = 0.f;
#pragma unroll
        for (int dy = 0; dy < 3; dy++) {
            if (cy == 0 && dy == 0) continue;
            if (cy == 2 && dy == 2) continue;
#pragma unroll
            for (int dx = 0; dx < 3; dx++) {
                if (cx == 0 && dx == 0) continue;
                if (cx == 2 && dx == 2) continue;
                s += w[ci * 9 + dy * 3 + dx];
            }
        }
        Wq[((br * 9 + cls) * 512 + co) * 5 + ci] = s;
    }
}

// ---------------- NCHW float -> padded channel-last fp16 (interior only) ------
__global__ void pad_convert(const float* __restrict__ src, __half* __restrict__ hi, int C) {
    int n = blockIdx.x, c0 = blockIdx.y * 64;
    __shared__ float tile[64][51];
    int tid = threadIdx.x;
    for (int e = tid; e < 64 * 49; e += 256) {
        int ci = e / 49, p = e - 49 * ci;
        tile[ci][p] = src[((size_t)n * C + c0 + ci) * 49 + p];
    }
    __syncthreads();
    for (int e = tid; e < 49 * 64; e += 256) {
        int p = e >> 6, ci = e & 63;
        int y = p / 7, x = p - 7 * y;
        hi[((size_t)n * 81 + (y + 1) * 9 + (x + 1)) * C + c0 + ci] =
            __float2half_rn(tile[ci][p]);
    }
}

// -------- combine 3 NCHW partials -> featCL (channel-last fp32) + fpad (fp16) --
__global__ void combine3_pad(const float* __restrict__ p0, const float* __restrict__ p1,
                             const float* __restrict__ p2,
                             float* __restrict__ featCL, __half* __restrict__ fpad) {
    int n = blockIdx.x, c0 = blockIdx.y * 64;
    __shared__ float tile[64][51];
    int tid = threadIdx.x;
    for (int e = tid; e < 64 * 49; e += 256) {
        int ci = e / 49, p = e - 49 * ci;
        size_t idx = ((size_t)n * CH + c0 + ci) * 49 + p;
        tile[ci][p] = p0[idx] + p1[idx] + p2[idx];
    }
    __syncthreads();
    for (int e = tid; e < 49 * 64; e += 256) {
        int p = e >> 6, ci = e & 63;
        float v = tile[ci][p];
        featCL[((size_t)n * 49 + p) * CH + c0 + ci] = v;        // channel-last, coalesced
        int y = p / 7, x = p - 7 * y;
        fpad[((size_t)n * 81 + (y + 1) * 9 + (x + 1)) * CH + c0 + ci] =
            __float2half_rn(v);
    }
}

// ------- fused GN-normalize + relu + pad-convert, channel-last, elementwise ---
__global__ void norm_relu_pad(const float* __restrict__ x1, const float* __restrict__ x2,
                              const float* __restrict__ stats,
                              const float* __restrict__ gamma, const float* __restrict__ beta,
                              __half* __restrict__ h1, __half* __restrict__ h2) {
    int idx = blockIdx.x * 256 + threadIdx.x;
    if (idx >= FEAT_ELEMS) return;
    int br = blockIdx.y;
    const float* x = br ? x2 : x1;
    __half* hp = br ? h2 : h1;
    int c = idx & 511;
    int t = idx >> 9;
    int n = t / 49, p = t - 49 * n;
    float mu = stats[br * 512 + n];
    float rs = stats[br * 512 + 256 + n];
    float v = fmaxf((x[idx] - mu) * rs * gamma[c] + beta[c], 0.f);
    int y = p / 7, xq = p - 7 * y;
    hp[((size_t)n * 81 + (y + 1) * 9 + (xq + 1)) * CH + c] = __float2half_rn(v);
}

// ---------------- batched HMMA conv (EXACT R12 body) --------------------------
#define KC   64
#define KCP  72
#define MATH (128*KCP)
#define BUFE (2*MATH)
#define NSTG 3
#define SMEM_BYTES (NSTG*BUFE*2)     // 110592 bytes

struct ConvBatch {
    const __half* a[4];
    const __half* wh[4];
    float* out[4];
    const float* addsrc;
    int tap0[4];
    int chlast;
};

__global__ void __launch_bounds__(256, 2)
conv_mma(ConvBatch P, int C, int ntap) {
    extern __shared__ __half smem[];
    const int K9 = 9 * C;
    const int NCI = C / KC;
    const int NQ = ntap * NCI;
    const int cv = blockIdx.z;
    const __half* __restrict__ A  = P.a[cv];
    const __half* __restrict__ Wh = P.wh[cv];
    float* __restrict__ out = P.out[cv];
    const float* addsrc = P.addsrc;
    const int tap0 = P.tap0[cv];

    const int tid = threadIdx.x;
    const int wid = tid >> 5, lane = tid & 31;
    const int g = lane >> 2, tg = lane & 3;
    const int m0 = blockIdx.x * 128;
    const int n0 = blockIdx.y * 128;
    const int wm = (wid & 1) * 64;
    const int wn = (wid >> 1) * 32;

    const int seg = tid & 7;
    const int r0 = tid >> 3;
    size_t abase[4];
#pragma unroll
    for (int h = 0; h < 4; h++) {
        int m = m0 + r0 + 32 * h;
        int n = m / 49, p = m - 49 * n;
        int y = p / 7, x = p - 7 * y;
        abase[h] = ((size_t)n * 81 + y * 9 + x) * C + seg * 8;
    }

    const int aRow = wm + (lane & 15);
    const int aCol = (lane >> 4) * 8;
    const int bRow = wn + (lane & 7) + ((lane >> 4) * 8);
    const int bCol = ((lane >> 3) & 1) * 8;

    auto fill = [&](int q) {
        __half* base = smem + (q % NSTG) * BUFE;
        int t = tap0 + q / NCI;
        int ci = (q % NCI) * KC;
        int a3 = t / 3, b3 = t - 3 * a3;
        size_t tof = (size_t)(a3 * 9 + b3) * C + ci;
#pragma unroll
        for (int h = 0; h < 4; h++) {
            int r = r0 + 32 * h;
            cp_async16(smem_u32(&base[r * KCP + seg * 8]), A + abase[h] + tof);
        }
#pragma unroll
        for (int h = 0; h < 4; h++) {
            int row = r0 + 32 * h;
            size_t src = (size_t)(n0 + row) * K9 + t * C + ci + seg * 8;
            cp_async16(smem_u32(&base[MATH + row * KCP + seg * 8]), Wh + src);
        }
        asm volatile("cp.async.commit_group;" ::: "memory");
    };

    float acc[4][4][4];
#pragma unroll
    for (int t = 0; t < 4; t++)
#pragma unroll
        for (int u = 0; u < 4; u++)
#pragma unroll
            for (int e = 0; e < 4; e++) acc[t][u][e] = 0.f;

    fill(0);
    if (NQ > 1) fill(1);

    for (int q = 0; q < NQ; q++) {
        if (q + 1 < NQ) asm volatile("cp.async.wait_group 1;" ::: "memory");
        else            asm volatile("cp.async.wait_group 0;" ::: "memory");
        __syncthreads();
        if (q + 2 < NQ) fill(q + 2);

        __half* cur = smem + (q % NSTG) * BUFE;
        uint32_t aB = smem_u32(cur);
        uint32_t bB = aB + MATH * 2;
#pragma unroll
        for (int s = 0; s < 4; s++) {
            uint32_t bregs[8];
            ldm_x4(bregs,     bB + (uint32_t)((bRow)      * KCP + 16 * s + bCol) * 2);
            ldm_x4(bregs + 4, bB + (uint32_t)((bRow + 16) * KCP + 16 * s + bCol) * 2);
#pragma unroll
            for (int t = 0; t < 4; t++) {
                uint32_t ar[4];
                ldm_x4(ar, aB + (uint32_t)((aRow + 16 * t) * KCP + 16 * s + aCol) * 2);
#pragma unroll
                for (int u = 0; u < 4; u++)
                    mma_f16(acc[t][u], ar, bregs + 2 * u);
            }
        }
    }

    // ---- epilogue (R12) ----
    if (P.chlast) {
#pragma unroll
        for (int t = 0; t < 4; t++) {
#pragma unroll
            for (int h = 0; h < 2; h++) {
                int row = m0 + wm + 16 * t + g + 8 * h;
                size_t base = (size_t)row * CH;
#pragma unroll
                for (int u = 0; u < 4; u++) {
                    int col = n0 + wn + 8 * u + tg * 2;
                    float2 v2 = make_float2(acc[t][u][2 * h], acc[t][u][2 * h + 1]);
                    *reinterpret_cast<float2*>(&out[base + col]) = v2;
                }
            }
        }
    } else {
#pragma unroll
        for (int t = 0; t < 4; t++) {
#pragma unroll
            for (int h = 0; h < 2; h++) {
                int row = m0 + wm + 16 * t + g + 8 * h;
                int n = row / 49, p = row - 49 * n;
                size_t base = (size_t)n * CH * 49 + p;
#pragma unroll
                for (int u = 0; u < 4; u++) {
                    int col = n0 + wn + 8 * u + tg * 2;
                    size_t i0 = base + (size_t)col * 49;
                    float v0 = acc[t][u][2 * h];
                    float v1 = acc[t][u][2 * h + 1];
                    if (addsrc) { v0 += addsrc[i0]; v1 += addsrc[i0 + 49]; }
                    out[i0] = v0;
                    out[i0 + 49] = v1;
                }
            }
        }
    }
}

// ------- out-conv variant: same mainloop, transpose epilogue (separate kernel) --
__global__ void __launch_bounds__(256, 2)
conv_mma_t(ConvBatch P, int C, int ntap) {
    extern __shared__ __half smem[];
    const int K9 = 9 * C;
    const int NCI = C / KC;
    const int NQ = ntap * NCI;
    const int cv = blockIdx.z;
    const __half* __restrict__ A  = P.a[cv];
    const __half* __restrict__ Wh = P.wh[cv];
    float* __restrict__ out = P.out[cv];
    const float* addsrc = P.addsrc;
    const int tap0 = P.tap0[cv];

    const int tid = threadIdx.x;
    const int wid = tid >> 5, lane = tid & 31;
    const int g = lane >> 2, tg = lane & 3;
    const int m0 = blockIdx.x * 128;
    const int n0 = blockIdx.y * 128;
    const int wm = (wid & 1) * 64;
    const int wn = (wid >> 1) * 32;

    const int seg = tid & 7;
    const int r0 = tid >> 3;
    size_t abase[4];
#pragma unroll
    for (int h = 0; h < 4; h++) {
        int m = m0 + r0 + 32 * h;
        int n = m / 49, p = m - 49 * n;
        int y = p / 7, x = p - 7 * y;
        abase[h] = ((size_t)n * 81 + y * 9 + x) * C + seg * 8;
    }

    const int aRow = wm + (lane & 15);
    const int aCol = (lane >> 4) * 8;
    const int bRow = wn + (lane & 7) + ((lane >> 4) * 8);
    const int bCol = ((lane >> 3) & 1) * 8;

    auto fill = [&](int q) {
        __half* base = smem + (q % NSTG) * BUFE;
        int t = tap0 + q / NCI;
        int ci = (q % NCI) * KC;
        int a3 = t / 3, b3 = t - 3 * a3;
        size_t tof = (size_t)(a3 * 9 + b3) * C + ci;
#pragma unroll
        for (int h = 0; h < 4; h++) {
            int r = r0 + 32 * h;
            cp_async16(smem_u32(&base[r * KCP + seg * 8]), A + abase[h] + tof);
        }
#pragma unroll
        for (int h = 0; h < 4; h++) {
            int row = r0 + 32 * h;
            size_t src = (size_t)(n0 + row) * K9 + t * C + ci + seg * 8;
            cp_async16(smem_u32(&base[MATH + row * KCP + seg * 8]), Wh + src);
        }
        asm volatile("cp.async.commit_group;" ::: "memory");
    };

    float acc[4][4][4];
#pragma unroll
    for (int t = 0; t < 4; t++)
#pragma unroll
        for (int u = 0; u < 4; u++)
#pragma unroll
            for (int e = 0; e < 4; e++) acc[t][u][e] = 0.f;

    fill(0);
    if (NQ > 1) fill(1);

    for (int q = 0; q < NQ; q++) {
        if (q + 1 < NQ) asm volatile("cp.async.wait_group 1;" ::: "memory");
        else            asm volatile("cp.async.wait_group 0;" ::: "memory");
        __syncthreads();
        if (q + 2 < NQ) fill(q + 2);

        __half* cur = smem + (q % NSTG) * BUFE;
        uint32_t aB = smem_u32(cur);
        uint32_t bB = aB + MATH * 2;
#pragma unroll
        for (int s = 0; s < 4; s++) {
            uint32_t bregs[8];
            ldm_x4(bregs,     bB + (uint32_t)((bRow)      * KCP + 16 * s + bCol) * 2);
            ldm_x4(bregs + 4, bB + (uint32_t)((bRow + 16) * KCP + 16 * s + bCol) * 2);
#pragma unroll
            for (int t = 0; t < 4; t++) {
                uint32_t ar[4];
                ldm_x4(ar, aB + (uint32_t)((aRow + 16 * t) * KCP + 16 * s + aCol) * 2);
#pragma unroll
                for (int u = 0; u < 4; u++)
                    mma_f16(acc[t][u], ar, bregs + 2 * u);
            }
        }
    }

    // ---- transpose epilogue: addsrc channel-last read, NCHW coalesced store ----
    float* sf = reinterpret_cast<float*>(smem);
    __syncthreads();
#pragma unroll
    for (int t = 0; t < 4; t++) {
#pragma unroll
        for (int h = 0; h < 2; h++) {
            int row = wm + 16 * t + g + 8 * h;
#pragma unroll
            for (int u = 0; u < 4; u++) {
                int col = wn + 8 * u + tg * 2;
                float2 a2 = *reinterpret_cast<const float2*>(
                    &addsrc[(size_t)(m0 + row) * CH + n0 + col]);
                sf[row * 129 + col]     = acc[t][u][2 * h] + a2.x;
                sf[row * 129 + col + 1] = acc[t][u][2 * h + 1] + a2.y;
            }
        }
    }
    __syncthreads();
    for (int e = tid; e < 128 * 128; e += 256) {
        int co = e >> 7, m = e & 127;      // consecutive threads vary m -> coalesced
        int mm = m0 + m;
        int n = mm / 49, p = mm - 49 * n;
        out[(size_t)n * CH * 49 + (size_t)(n0 + co) * 49 + p] = sf[m * 129 + co];
    }
}

// ------- attention per (hw, g, br); q computed on the fly from Wq x s5 --------
#define CCH 256
__global__ void attn2(const float* __restrict__ status, const float* __restrict__ rois,
                      const float* __restrict__ Wq,
                      const float* __restrict__ k1, const float* __restrict__ v1,
                      float* __restrict__ w1,
                      const float* __restrict__ k2, const float* __restrict__ v2,
                      float* __restrict__ w2) {
    int hw = blockIdx.x;
    int gg = blockIdx.y;
    int br = blockIdx.z;
    const float* k = br ? k2 : k1;
    const float* v = br ? v2 : v1;
    float* virt = br ? w2 : w1;

    int yy = hw / 7, xx = hw - 7 * yy;
    int cy = (yy == 0) ? 0 : ((yy == 6) ? 2 : 1);
    int cx = (xx == 0) ? 0 : ((xx == 6) ? 2 : 1);
    const float* WqBase = Wq + ((size_t)(br * 9 + cy * 3 + cx) * 512) * 5;

    __shared__ float bufA[GSZ][CCH + 1];
    __shared__ float bufB[GSZ][CCH + 1];
    __shared__ float att[GSZ][GSZ + 1];
    __shared__ float attn[GSZ][GSZ + 1];
    __shared__ float s5[GSZ][5];
    __shared__ float wqs[CCH][5];

    int tid = threadIdx.x;
    int i = tid >> 4, j = tid & 15;

    if (tid < GSZ * 5) {
        int r = tid / 5, ci = tid - 5 * r;
        int n = gg * GSZ + r;
        s5[r][ci] = (ci == 0) ? status[n * 2 + br] : rois[n * 5 + ci];
    }
    __syncthreads();

    float a = 0.f;
    for (int c0 = 0; c0 < CH; c0 += CCH) {
        for (int e = tid; e < CCH * 5; e += 256)
            wqs[e / 5][e % 5] = WqBase[(size_t)(c0 + e / 5) * 5 + (e % 5)];
        for (int e = tid; e < GSZ * CCH; e += 256) {
            int r = e >> 8, c = e & 255;
            bufB[r][c] = k[((size_t)(gg * GSZ + r) * 49 + hw) * CH + c0 + c];
        }
        __syncthreads();
        for (int e = tid; e < GSZ * CCH; e += 256) {
            int r = e >> 8, c = e & 255;
            bufA[r][c] = wqs[c][0] * s5[r][0] + wqs[c][1] * s5[r][1]
                       + wqs[c][2] * s5[r][2] + wqs[c][3] * s5[r][3]
                       + wqs[c][4] * s5[r][4];
        }
        __syncthreads();
#pragma unroll 8
        for (int c = 0; c < CCH; c++)
            a += bufA[i][c] * bufB[j][c];
        __syncthreads();
    }
    att[i][j] = a * ATT_SCALE;
    __syncthreads();

    float mx = att[i][0];
#pragma unroll
    for (int jj = 1; jj < GSZ; jj++) mx = fmaxf(mx, att[i][jj]);
    float sum = 0.f;
#pragma unroll
    for (int jj = 0; jj < GSZ; jj++) sum += expf(att[i][jj] - mx);
    attn[i][j] = expf(att[i][j] - mx) / sum;
    __syncthreads();

    for (int c0 = 0; c0 < CH; c0 += CCH) {
        for (int e = tid; e < GSZ * CCH; e += 256) {
            int r = e >> 8, c = e & 255;
            bufA[r][c] = v[((size_t)(gg * GSZ + r) * 49 + hw) * CH + c0 + c];
        }
        __syncthreads();
        for (int e = tid; e < GSZ * CCH; e += 256) {
            int r = e >> 8, c = e & 255;
            float s = 0.f;
#pragma unroll
            for (int jj = 0; jj < GSZ; jj++) s += attn[r][jj] * bufA[jj][c];
            virt[((size_t)(gg * GSZ + r) * 49 + hw) * CH + c0 + c] = s;
        }
        __syncthreads();
    }
}

// ---------------- groupnorm stats, both branches ----------
__global__ void gn_stats2(const float* __restrict__ x1, const float* __restrict__ x2,
                          float* __restrict__ stats) {
    __shared__ float ss[256], sq[256];
    int blk = blockIdx.x;
    int br = blk >> 8, n = blk & 255;
    const float* p = (br ? x2 : x1) + (size_t)n * CH * HW;
    float a = 0.f, b = 0.f;
    for (int e = threadIdx.x; e < CH * HW; e += 256) {
        float v = p[e];
        a += v; b += v * v;
    }
    ss[threadIdx.x] = a; sq[threadIdx.x] = b;
    __syncthreads();
    for (int s = 128; s > 0; s >>= 1) {
        if (threadIdx.x < s) { ss[threadIdx.x] += ss[threadIdx.x + s]; sq[threadIdx.x] += sq[threadIdx.x + s]; }
        __syncthreads();
    }
    if (threadIdx.x == 0) {
        float m = ss[0] / (float)(CH * HW);
        float var = sq[0] / (float)(CH * HW) - m * m;
        stats[br * 512 + n] = m;
        stats[br * 512 + 256 + n] = rsqrtf(var + EPSG);
    }
}

// ---------------- launcher ----------------
extern "C" void kernel_launch(void* const* d_in, const int* in_sizes, int n_in,
                              void* d_out, int out_size) {
    const float* status = (const float*)d_in[0];
    const float* rois   = (const float*)d_in[1];
    const float* bbox   = (const float*)d_in[2];
    const float* wR     = (const float*)d_in[3];
    const float* wQ1    = (const float*)d_in[4];
    const float* wQ2    = (const float*)d_in[5];
    const float* wK1    = (const float*)d_in[6];
    const float* wV1    = (const float*)d_in[7];
    const float* wK2    = (const float*)d_in[8];
    const float* wV2    = (const float*)d_in[9];
    const float* wC1    = (const float*)d_in[10];
    const float* wC2    = (const float*)d_in[11];
    const float* gamma  = (const float*)d_in[12];
    const float* beta   = (const float*)d_in[13];
    float* out1 = (float*)d_out;
    float* out2 = out1 + FEAT_ELEMS;

    float *feat, *k1, *v1, *k2, *v2, *vir1, *vir2, *stats, *wqv;
    cudaGetSymbolAddress((void**)&feat, g_feat);
    cudaGetSymbolAddress((void**)&k1,   g_k1);
    cudaGetSymbolAddress((void**)&v1,   g_v1);
    cudaGetSymbolAddress((void**)&k2,   g_k2);
    cudaGetSymbolAddress((void**)&v2,   g_v2);
    cudaGetSymbolAddress((void**)&vir1, g_vir1);
    cudaGetSymbolAddress((void**)&vir2, g_vir2);
    cudaGetSymbolAddress((void**)&stats, g_stats);
    cudaGetSymbolAddress((void**)&wqv,  g_wq);

    __half *bpad, *fpad, *h1p, *h2p;
    cudaGetSymbolAddress((void**)&bpad, g_bpad);
    cudaGetSymbolAddress((void**)&fpad, g_fpad);
    cudaGetSymbolAddress((void**)&h1p,  g_h1pad);
    cudaGetSymbolAddress((void**)&h2p,  g_h2pad);

    __half *whR, *whK1, *whV1, *whK2, *whV2, *whC1, *whC2;
    cudaGetSymbolAddress((void**)&whR,  g_wR);
    cudaGetSymbolAddress((void**)&whK1, g_wK1);
    cudaGetSymbolAddress((void**)&whV1, g_wV1);
    cudaGetSymbolAddress((void**)&whK2, g_wK2);
    cudaGetSymbolAddress((void**)&whV2, g_wV2);
    cudaGetSymbolAddress((void**)&whC1, g_wC1);
    cudaGetSymbolAddress((void**)&whC2, g_wC2);

    cudaFuncSetAttribute(conv_mma, cudaFuncAttributeMaxDynamicSharedMemorySize, SMEM_BYTES);
    cudaFuncSetAttribute(conv_mma_t, cudaFuncAttributeMaxDynamicSharedMemorySize, SMEM_BYTES);

    // coalesced weight reorder + fp16 round (1 launch, all 7 weights)
    {
        WReorder2 R;
        R.src[0] = wR;  R.dst[0] = whR;  R.C[0] = CIN;
        R.src[1] = wK1; R.dst[1] = whK1; R.C[1] = CH;
        R.src[2] = wV1; R.dst[2] = whV1; R.C[2] = CH;
        R.src[3] = wK2; R.dst[3] = whK2; R.C[3] = CH;
        R.src[4] = wV2; R.dst[4] = whV2; R.C[4] = CH;
        R.src[5] = wC1; R.dst[5] = whC1; R.C[5] = CH;
        R.src[6] = wC2; R.dst[6] = whC2; R.C[6] = CH;
        int x = 0;
        for (int ci0 = 0; ci0 < CIN; ci0 += 256) { R.sidx[x] = 0; R.ci0[x] = ci0; x++; }
        for (int s = 1; s < 7; s++)
            for (int ci0 = 0; ci0 < CH; ci0 += 256) { R.sidx[x] = s; R.ci0[x] = ci0; x++; }
        conv_w_reorder2<<<dim3(x, CH), 256>>>(R);   // x = 21
    }

    // q-conv weight collapse
    qw_prep<<<(2 * 9 * 512 + 255) / 256, 256>>>(wQ1, wQ2, wqv);

    // pad-convert bbox
    pad_convert<<<dim3(NSAMP, CIN / 64), 256>>>(bbox, bpad, CIN);

    // reduce conv split-K=3 (NCHW partials, R12 epilogue)
    {
        ConvBatch P = {};
        for (int z = 0; z < 3; z++) { P.a[z] = bpad; P.wh[z] = whR; P.tap0[z] = 3 * z; }
        P.out[0] = k1; P.out[1] = v1; P.out[2] = k2;
        P.addsrc = nullptr; P.chlast = 0;
        conv_mma<<<dim3(NSAMP * HW / 128, CH / 128, 3), 256, SMEM_BYTES>>>(P, CIN, 3);
    }

    // combine partials -> featCL (channel-last fp32) + fpad (fp16 padded)
    combine3_pad<<<dim3(NSAMP, CH / 64), 256>>>(k1, v1, k2, feat, fpad);

    // k/v convs (4 fused), channel-last outputs
    {
        ConvBatch P = {};
        for (int i = 0; i < 4; i++) { P.a[i] = fpad; P.tap0[i] = 0; }
        P.wh[0] = whK1; P.out[0] = k1;
        P.wh[1] = whV1; P.out[1] = v1;
        P.wh[2] = whK2; P.out[2] = k2;
        P.wh[3] = whV2; P.out[3] = v2;
        P.addsrc = nullptr; P.chlast = 1;
        conv_mma<<<dim3(NSAMP * HW / 128, CH / 128, 4), 256, SMEM_BYTES>>>(P, CH, 9);
    }

    // attention (q fused from Wq x s5), both branches
    attn2<<<dim3(HW, NG, 2), 256>>>(status, rois, wqv, k1, v1, vir1, k2, v2, vir2);

    // groupnorm stats, both branches
    gn_stats2<<<512, 256>>>(vir1, vir2, stats);

    // fused normalize+relu+pad-convert, elementwise channel-last
    norm_relu_pad<<<dim3((FEAT_ELEMS + 255) / 256, 2), 256>>>(vir1, vir2, stats,
                                                              gamma, beta, h1p, h2p);

    // out convs (2 fused): out = featCL + conv(h, w_c), separate transpose kernel
    {
        ConvBatch P = {};
        P.a[0] = h1p; P.wh[0] = whC1; P.out[0] = out1; P.tap0[0] = 0;
        P.a[1] = h2p; P.wh[1] = whC2; P.out[1] = out2; P.tap0[1] = 0;
        P.addsrc = feat; P.chlast = 0;
        conv_mma_t<<<dim3(NSAMP * HW / 128, CH / 128, 2), 256, SMEM_BYTES>>>(P, CH, 9);
    }
}